// round 4
// baseline (speedup 1.0000x reference)
#include <cuda_runtime.h>
#include <math.h>
#include <stdint.h>

// ---------------------------------------------------------------------------
// KNRM fused kernel (Round 3: FFMA2 f32x2 GEMM + double-buffered gather)
//   per CTA: one (pair, batch): gather+norm Q/D embeddings, 32x256 cosine GEMM
//   (packed-f32x2 FFMA2, K-chunked double-buffered smem), 21 Gaussian bins,
//   log1p-sum, 3-layer MLP.  Kernel 2: sigmoid(l1 - l2).
// ---------------------------------------------------------------------------

#define THREADS   256
#define QLEN      32
#define DLEN      256
#define EMB_D     256
#define KCHUNK    32
#define NKC       (EMB_D / KCHUNK)      // 8
#define QT_PITCH  36                    // 32 + 4 pad (144B rows, 16B aligned)
#define DT_PITCH  260                   // 256 + 4   (1040B rows, 16B aligned)
#define KNUM      21
#define BATCH     512

// -0.5/sigma^2 * log2(e) constants for exp2-based Gaussian
#define K2L  (-72.13475204444817f)       // sigma = 0.1
#define K2E  (-721347.5204444817f)       // sigma = 0.001

struct SmemLayout {
    float qT[EMB_D][QT_PITCH];            // transposed query embeddings [k][q]
    float dT[2][KCHUNK][DT_PITCH];        // double-buffered doc chunk   [k][d]
    float qscale[QLEN];
    float dscale[DLEN];
    float qpart[8][QLEN];                 // per-warp partial sumsq for q rows
    float kpart[2][QLEN][KNUM];           // per-d-half kernel sums
    float km[KNUM];
};

__device__ float g_logits[2][BATCH];

__device__ __forceinline__ float fast_ex2(float x) {
    float y;
    asm("ex2.approx.ftz.f32 %0, %1;" : "=f"(y) : "f"(x));
    return y;
}

__device__ __forceinline__ unsigned long long dup_f32x2(float v) {
    unsigned long long r;
    asm("mov.b64 %0, {%1, %1};" : "=l"(r) : "f"(v));
    return r;
}

__device__ __forceinline__ void ffma2(unsigned long long& c,
                                      unsigned long long a,
                                      unsigned long long b) {
    asm("fma.rn.f32x2 %0, %1, %2, %0;" : "+l"(c) : "l"(a), "l"(b));
}

__device__ __forceinline__ void unpack_f32x2(unsigned long long v,
                                             float& lo, float& hi) {
    asm("mov.b64 {%0, %1}, %2;" : "=f"(lo), "=f"(hi) : "l"(v));
}

__global__ void __launch_bounds__(THREADS, 2)
knrm_main(const int* __restrict__ q1, const int* __restrict__ d1,
          const int* __restrict__ q2, const int* __restrict__ d2,
          const float* __restrict__ emb,
          const float* __restrict__ W0, const float* __restrict__ b0,
          const float* __restrict__ W1, const float* __restrict__ b1,
          const float* __restrict__ W2, const float* __restrict__ b2)
{
    extern __shared__ unsigned char smem_raw[];
    SmemLayout& S = *reinterpret_cast<SmemLayout*>(smem_raw);

    const int b    = blockIdx.x;
    const int pair = blockIdx.y;
    const int* qtok_g = (pair == 0 ? q1 : q2) + b * QLEN;
    const int* dtok_g = (pair == 0 ? d1 : d2) + b * DLEN;

    const int t = threadIdx.x;
    const int w = t >> 5;     // warp 0..7
    const int L = t & 31;     // lane

    // ---- Load Q embeddings: warp w loads cols [32w,32w+32) of all 32 rows,
    //      lane <-> row.  Transposed STS is conflict-free.
    {
        const int   tok = qtok_g[L];
        const float* row = emb + (size_t)tok * EMB_D + w * 32;
        float ss = 0.f;
        #pragma unroll
        for (int i = 0; i < 8; i++) {
            float4 v = *(const float4*)(row + 4 * i);
            int k = w * 32 + 4 * i;
            S.qT[k + 0][L] = v.x;
            S.qT[k + 1][L] = v.y;
            S.qT[k + 2][L] = v.z;
            S.qT[k + 3][L] = v.w;
            ss = fmaf(v.x, v.x, ss);
            ss = fmaf(v.y, v.y, ss);
            ss = fmaf(v.z, v.z, ss);
            ss = fmaf(v.w, v.w, ss);
        }
        S.qpart[w][L] = ss;
    }

    // ---- GEMM mapping: warp w -> q rows [q0, q0+8), doc half dhalf.
    const int q0    = (w & 3) * 8;
    const int dhalf = w >> 2;
    const int dbase = dhalf * 128;
    // gather row for this thread
    const int drow_id = t;
    const int dtok = dtok_g[drow_id];
    const float* drow = emb + (size_t)dtok * EMB_D;

    float dss = 0.f;
    float4 ld[KCHUNK / 4];                 // prefetch buffer (8 x float4)

    // prologue: fetch chunk 0 and store
    #pragma unroll
    for (int i = 0; i < KCHUNK / 4; i++) ld[i] = *(const float4*)(drow + 4 * i);
    #pragma unroll
    for (int i = 0; i < KCHUNK / 4; i++) {
        float4 v = ld[i];
        int kk = 4 * i;
        S.dT[0][kk + 0][drow_id] = v.x;
        S.dT[0][kk + 1][drow_id] = v.y;
        S.dT[0][kk + 2][drow_id] = v.z;
        S.dT[0][kk + 3][drow_id] = v.w;
        dss = fmaf(v.x, v.x, dss);
        dss = fmaf(v.y, v.y, dss);
        dss = fmaf(v.z, v.z, dss);
        dss = fmaf(v.w, v.w, dss);
    }
    __syncthreads();

    // ---- Q norms (warp 0) — after sync1 so qpart is complete
    if (w == 0) {
        float ss = 0.f;
        #pragma unroll
        for (int i = 0; i < 8; i++) ss += S.qpart[i][L];
        S.qscale[L] = 1.0f / fmaxf(sqrtf(ss), 1e-8f);
    }

    // ---- Main loop: C[32x256] in registers as f32x2 pairs.
    //      C2[i][j] halves = ( C[q0+2i][dj] , C[q0+2i+1][dj] )
    unsigned long long C2[4][4];
    #pragma unroll
    for (int i = 0; i < 4; i++)
        #pragma unroll
        for (int j = 0; j < 4; j++) C2[i][j] = 0ull;

    for (int kc = 0; kc < NKC; kc++) {
        const int cur = kc & 1;
        // issue next chunk's LDGs early (latency hides under GEMM)
        if (kc + 1 < NKC) {
            const float* src = drow + (kc + 1) * KCHUNK;
            #pragma unroll
            for (int i = 0; i < KCHUNK / 4; i++)
                ld[i] = *(const float4*)(src + 4 * i);
        }

        // GEMM over this K-chunk
        #pragma unroll 8
        for (int kk = 0; kk < KCHUNK; kk++) {
            const float* qrow = &S.qT[kc * KCHUNK + kk][q0];
            ulonglong2 qa = *(const ulonglong2*)(qrow);       // (q0,q1)(q2,q3)
            ulonglong2 qb = *(const ulonglong2*)(qrow + 4);   // (q4,q5)(q6,q7)
            float4 dv = *(const float4*)(&S.dT[cur][kk][dbase + 4 * L]);
            unsigned long long d2[4];
            d2[0] = dup_f32x2(dv.x);
            d2[1] = dup_f32x2(dv.y);
            d2[2] = dup_f32x2(dv.z);
            d2[3] = dup_f32x2(dv.w);
            unsigned long long qp[4] = {qa.x, qa.y, qb.x, qb.y};
            #pragma unroll
            for (int i = 0; i < 4; i++)
                #pragma unroll
                for (int j = 0; j < 4; j++)
                    ffma2(C2[i][j], qp[i], d2[j]);
        }

        // store next chunk into the other buffer (safe: last read of that
        // buffer finished before the sync at end of previous iteration)
        if (kc + 1 < NKC) {
            const int nxt = (kc + 1) & 1;
            #pragma unroll
            for (int i = 0; i < KCHUNK / 4; i++) {
                float4 v = ld[i];
                int kk = 4 * i;
                S.dT[nxt][kk + 0][drow_id] = v.x;
                S.dT[nxt][kk + 1][drow_id] = v.y;
                S.dT[nxt][kk + 2][drow_id] = v.z;
                S.dT[nxt][kk + 3][drow_id] = v.w;
                dss = fmaf(v.x, v.x, dss);
                dss = fmaf(v.y, v.y, dss);
                dss = fmaf(v.z, v.z, dss);
                dss = fmaf(v.w, v.w, dss);
            }
        }
        __syncthreads();
    }

    S.dscale[drow_id] = 1.0f / fmaxf(sqrtf(dss), 1e-8f);
    __syncthreads();

    // ---- Gaussian soft-binning.
    {
        float C[8][4];
        #pragma unroll
        for (int i = 0; i < 4; i++)
            #pragma unroll
            for (int j = 0; j < 4; j++)
                unpack_f32x2(C2[i][j], C[2 * i][j], C[2 * i + 1][j]);

        float qs[8];
        #pragma unroll
        for (int qi = 0; qi < 8; qi++) qs[qi] = S.qscale[q0 + qi];
        float4 ds4 = *(const float4*)(&S.dscale[dbase + 4 * L]);
        float ds[4] = {ds4.x, ds4.y, ds4.z, ds4.w};

        #pragma unroll
        for (int qi = 0; qi < 8; qi++) {
            float kacc[KNUM];
            #pragma unroll
            for (int k = 0; k < KNUM; k++) kacc[k] = 0.f;

            #pragma unroll
            for (int j = 0; j < 4; j++) {
                float x = C[qi][j] * (qs[qi] * ds[j]);   // cosine sim
                #pragma unroll
                for (int k = 0; k < 20; k++) {
                    float d0 = x - (-0.95f + 0.1f * (float)k);
                    kacc[k] += fast_ex2(d0 * d0 * K2L);
                }
                float de = x - 1.0f;                      // exact-match kernel
                kacc[20] += fast_ex2(de * de * K2E);
            }

            // warp-reduce over 32 lanes (covers this warp's 128 doc cols)
            #pragma unroll
            for (int k = 0; k < KNUM; k++) {
                float v = kacc[k];
                v += __shfl_xor_sync(0xffffffffu, v, 16);
                v += __shfl_xor_sync(0xffffffffu, v, 8);
                v += __shfl_xor_sync(0xffffffffu, v, 4);
                v += __shfl_xor_sync(0xffffffffu, v, 2);
                v += __shfl_xor_sync(0xffffffffu, v, 1);
                if (L == 0) S.kpart[dhalf][q0 + qi][k] = v;
            }
        }
    }
    __syncthreads();

    // ---- km[k] = sum_q log1p(kpart[0][q][k] + kpart[1][q][k])
    if (t < KNUM) {
        float s = 0.f;
        #pragma unroll 4
        for (int q = 0; q < QLEN; q++)
            s += log1pf(S.kpart[0][q][t] + S.kpart[1][q][t]);
        S.km[t] = s;
    }
    __syncthreads();

    // ---- tiny MLP (thread 0)
    if (t == 0) {
        float h0[10];
        #pragma unroll
        for (int o = 0; o < 10; o++) {
            float acc = b0[o];
            #pragma unroll
            for (int k = 0; k < KNUM; k++) acc = fmaf(S.km[k], W0[o * KNUM + k], acc);
            h0[o] = fmaxf(acc, 0.f);
        }
        float h1[5];
        #pragma unroll
        for (int o = 0; o < 5; o++) {
            float acc = b1[o];
            #pragma unroll
            for (int i = 0; i < 10; i++) acc = fmaf(h0[i], W1[o * 10 + i], acc);
            h1[o] = fmaxf(acc, 0.f);
        }
        float l = b2[0];
        #pragma unroll
        for (int i = 0; i < 5; i++) l = fmaf(h1[i], W2[i], l);
        g_logits[pair][b] = l;
    }
}

__global__ void knrm_final(float* __restrict__ out)
{
    int b = blockIdx.x * blockDim.x + threadIdx.x;
    if (b < BATCH) {
        float d = g_logits[0][b] - g_logits[1][b];
        out[b] = 1.0f / (1.0f + expf(-d));
    }
}

extern "C" void kernel_launch(void* const* d_in, const int* in_sizes, int n_in,
                              void* d_out, int out_size)
{
    (void)in_sizes; (void)n_in; (void)out_size;
    const int*   q1  = (const int*)d_in[0];
    const int*   dd1 = (const int*)d_in[1];
    const int*   q2  = (const int*)d_in[2];
    const int*   dd2 = (const int*)d_in[3];
    const float* emb = (const float*)d_in[4];
    const float* W0  = (const float*)d_in[5];
    const float* b0  = (const float*)d_in[6];
    const float* W1  = (const float*)d_in[7];
    const float* b1  = (const float*)d_in[8];
    const float* W2  = (const float*)d_in[9];
    const float* b2  = (const float*)d_in[10];

    const int smem_bytes = (int)sizeof(SmemLayout);
    cudaFuncSetAttribute(knrm_main, cudaFuncAttributeMaxDynamicSharedMemorySize,
                         smem_bytes);

    dim3 grid(BATCH, 2);
    knrm_main<<<grid, THREADS, smem_bytes>>>(q1, dd1, q2, dd2, emb,
                                             W0, b0, W1, b1, W2, b2);
    knrm_final<<<(BATCH + 255) / 256, 256>>>((float*)d_out);
}